// round 7
// baseline (speedup 1.0000x reference)
#include <cuda_runtime.h>
#include <math.h>

// Problem constants
#define NB   64     // batch
#define NL   32     // caption length
#define NT   31     // decode steps = L-1
#define NV   16000  // vocab
#define NE   512    // ENC = DEC = ATT
#define NP   256    // pixels

#define GRIDN 128   // persistent kernel blocks (co-resident, 1 per SM)

// ---------------- device scratch (no allocation allowed) ----------------
__device__ float g_enc [NB * NP * NE];        // [B][P][C]
__device__ float g_att1[NB * NP * NE];        // [B][P][A]
__device__ float g_mean[NB * NE];
__device__ float g_h   [NB * NE];
__device__ float g_c   [NB * NE];
__device__ float g_Hall[NT * NB * NE];        // h2 per step (plain d layout)
__device__ float g_xprj[NT * NB * 2048];      // emb gates (INTERLEAVED 4d+g) + biases
__device__ float g_pA  [8 * NB * 3072];       // phase-A k-split partials
__device__ float g_pC  [8 * NB * 2048];       // phase-C k-split partials
__device__ float g_e   [NB * NP];             // attention scores
__device__ float g_awe [NB * NE];
__device__ float g_WA  [3072 * 512];          // [Wdec; Wbeta; Whh interleaved 4d+g]
__device__ float g_WCD [2048 * 512];          // Wih[:,256:768] rows interleaved 4d+g
__device__ float g_Wihx[2048 * 256];          // Wih[:,0:256]   rows interleaved 4d+g
__device__ float g_bsum[2048];                // (b_ih+b_hh) interleaved 4d+g
__device__ int   g_capx[2048];                // emb row per (t,b)
__device__ int   g_rowA[2048];                // active row -> t*64+b (into Hall)
__device__ int   g_rowO[2048];                // active row -> b*31+t (into out)
__device__ int   g_nact[1];
__device__ unsigned g_leaf[16 * 32];          // barrier leaf counters (128B apart)
__device__ unsigned g_cnt;                    // barrier root counter
__device__ unsigned g_rel;                    // barrier release phase

__device__ __forceinline__ float sigf(float x) { return 1.0f / (1.0f + expf(-x)); }

// ============================================================================
// High-throughput SGEMM: C[M,N] = A[M,K] * B[N,K]^T (+bias)  (45 TF/s measured)
// ============================================================================
__global__ void __launch_bounds__(256, 2)
sgemm128(const float* __restrict__ A, int lda, const int* __restrict__ arow,
         const float* __restrict__ B, int ldb,
         const float* __restrict__ bias,
         float* __restrict__ C, int ldc, const int* __restrict__ crow,
         int M, const int* __restrict__ Mdev, int K)
{
    int Mv = Mdev ? *Mdev : M;
    int m0 = blockIdx.x * 128;
    if (m0 >= Mv) return;
    int n0 = blockIdx.y * 128;

    __shared__ float As[2][8][128];
    __shared__ float Bs[2][8][128];

    int tid = threadIdx.x;
    int lrow = tid >> 1;
    int lk4  = (tid & 1) * 4;

    int rowm = m0 + lrow;
    int ca   = (rowm < Mv) ? rowm : (Mv - 1);
    int ar   = arow ? arow[ca] : ca;
    const float* Ap = A + (long long)ar * lda + lk4;
    const float* Bp = B + (long long)(n0 + lrow) * ldb + lk4;

    int tx = tid & 15;
    int ty = tid >> 4;

    float acc[8][8];
#pragma unroll
    for (int i = 0; i < 8; i++)
#pragma unroll
        for (int j = 0; j < 8; j++) acc[i][j] = 0.0f;

    {
        float4 a4 = *(const float4*)Ap;
        float4 b4 = *(const float4*)Bp;
        As[0][lk4 + 0][lrow] = a4.x; As[0][lk4 + 1][lrow] = a4.y;
        As[0][lk4 + 2][lrow] = a4.z; As[0][lk4 + 3][lrow] = a4.w;
        Bs[0][lk4 + 0][lrow] = b4.x; Bs[0][lk4 + 1][lrow] = b4.y;
        Bs[0][lk4 + 2][lrow] = b4.z; Bs[0][lk4 + 3][lrow] = b4.w;
    }
    __syncthreads();

    int ntiles = K >> 3;
    int buf = 0;
    for (int t = 0; t < ntiles; t++) {
        float4 na, nb;
        bool more = (t + 1 < ntiles);
        if (more) {
            int kk = (t + 1) << 3;
            na = *(const float4*)(Ap + kk);
            nb = *(const float4*)(Bp + kk);
        }
#pragma unroll
        for (int k = 0; k < 8; k++) {
            float a[8], b[8];
            *(float4*)(a)     = *(const float4*)&As[buf][k][ty * 4];
            *(float4*)(a + 4) = *(const float4*)&As[buf][k][64 + ty * 4];
            *(float4*)(b)     = *(const float4*)&Bs[buf][k][tx * 4];
            *(float4*)(b + 4) = *(const float4*)&Bs[buf][k][64 + tx * 4];
#pragma unroll
            for (int i = 0; i < 8; i++)
#pragma unroll
                for (int j = 0; j < 8; j++)
                    acc[i][j] = fmaf(a[i], b[j], acc[i][j]);
        }
        if (more) {
            int nbuf = buf ^ 1;
            As[nbuf][lk4 + 0][lrow] = na.x; As[nbuf][lk4 + 1][lrow] = na.y;
            As[nbuf][lk4 + 2][lrow] = na.z; As[nbuf][lk4 + 3][lrow] = na.w;
            Bs[nbuf][lk4 + 0][lrow] = nb.x; Bs[nbuf][lk4 + 1][lrow] = nb.y;
            Bs[nbuf][lk4 + 2][lrow] = nb.z; Bs[nbuf][lk4 + 3][lrow] = nb.w;
            __syncthreads();
            buf = nbuf;
        }
    }

    float bv[8];
#pragma unroll
    for (int jh = 0; jh < 2; jh++)
#pragma unroll
        for (int j = 0; j < 4; j++)
            bv[jh * 4 + j] = bias ? bias[n0 + jh * 64 + tx * 4 + j] : 0.0f;

#pragma unroll
    for (int i = 0; i < 8; i++) {
        int r = m0 + ((i < 4) ? (ty * 4 + i) : (64 + ty * 4 + i - 4));
        if (r >= Mv) continue;
        int cr = crow ? crow[r] : r;
        float* Cp = C + (long long)cr * ldc + n0;
#pragma unroll
        for (int jh = 0; jh < 2; jh++) {
            float4 v;
            v.x = acc[i][jh * 4 + 0] + bv[jh * 4 + 0];
            v.y = acc[i][jh * 4 + 1] + bv[jh * 4 + 1];
            v.z = acc[i][jh * 4 + 2] + bv[jh * 4 + 2];
            v.w = acc[i][jh * 4 + 3] + bv[jh * 4 + 3];
            *(float4*)(Cp + jh * 64 + tx * 4) = v;
        }
    }
}

// ---------------- small tiled SGEMM (h0/c0 only) ----------------------------
__global__ void sgemm64(const float* __restrict__ A, int lda,
                        const float* __restrict__ B, int ldb,
                        const float* __restrict__ bias,
                        float* __restrict__ C, int ldc, int K)
{
    int n0 = blockIdx.y * 64;
    __shared__ float As[16][68];
    __shared__ float Bs[16][68];

    int tid = threadIdx.x;
    int tx = tid & 15, ty = tid >> 4;
    int lm = tid >> 2, lk = (tid & 3) * 4;

    const float* Arow = A + (long long)lm * lda;
    const float* Brow = B + (long long)(n0 + lm) * ldb;

    float acc[4][4];
#pragma unroll
    for (int i = 0; i < 4; i++)
#pragma unroll
        for (int j = 0; j < 4; j++) acc[i][j] = 0.0f;

    for (int kk = 0; kk < K; kk += 16) {
        float4 av = *(const float4*)(Arow + kk + lk);
        float4 bv = *(const float4*)(Brow + kk + lk);
        __syncthreads();
        As[lk + 0][lm] = av.x; As[lk + 1][lm] = av.y;
        As[lk + 2][lm] = av.z; As[lk + 3][lm] = av.w;
        Bs[lk + 0][lm] = bv.x; Bs[lk + 1][lm] = bv.y;
        Bs[lk + 2][lm] = bv.z; Bs[lk + 3][lm] = bv.w;
        __syncthreads();
#pragma unroll
        for (int k = 0; k < 16; k++) {
            float4 a4 = *(const float4*)&As[k][ty * 4];
            float4 b4 = *(const float4*)&Bs[k][tx * 4];
            float aa[4] = {a4.x, a4.y, a4.z, a4.w};
            float bb[4] = {b4.x, b4.y, b4.z, b4.w};
#pragma unroll
            for (int i = 0; i < 4; i++)
#pragma unroll
                for (int j = 0; j < 4; j++) acc[i][j] = fmaf(aa[i], bb[j], acc[i][j]);
        }
    }

#pragma unroll
    for (int i = 0; i < 4; i++) {
        float* Cp = C + (long long)(ty * 4 + i) * ldc + n0 + tx * 4;
#pragma unroll
        for (int j = 0; j < 4; j++)
            Cp[j] = acc[i][j] + bias[n0 + tx * 4 + j];
    }
}

// ---------------- transpose encoder_out [B][C][P] -> enc [B][P][C] ----------
__global__ void transpose_enc(const float* __restrict__ eo, float* __restrict__ enc)
{
    __shared__ float t[32][33];
    int b = blockIdx.z;
    int c0 = blockIdx.x * 32, p0 = blockIdx.y * 32;
    int x = threadIdx.x, y = threadIdx.y;
    for (int i = y; i < 32; i += 8)
        t[i][x] = eo[((long long)b * NE + c0 + i) * NP + p0 + x];
    __syncthreads();
    for (int i = y; i < 32; i += 8)
        enc[((long long)b * NP + p0 + i) * NE + c0 + x] = t[x][i];
}

// ---------------- mean over pixels ------------------------------------------
__global__ void mean_kernel(const float* __restrict__ eo, float* __restrict__ mean)
{
    int row = blockIdx.x * 8 + threadIdx.y;
    int lane = threadIdx.x;
    const float* src = eo + (long long)row * NP;
    float s = 0.0f;
    for (int p = lane; p < NP; p += 32) s += src[p];
#pragma unroll
    for (int o = 16; o > 0; o >>= 1) s += __shfl_xor_sync(0xffffffffu, s, o);
    if (lane == 0) mean[row] = s * (1.0f / NP);
}

// ---------------- setup (also resets barrier state every replay) ------------
__global__ void setup_kernel(const int* __restrict__ caps, const int* __restrict__ lens,
                             const float* __restrict__ b_ih, const float* __restrict__ b_hh)
{
    int tid = threadIdx.x;
    for (int j = tid; j < 2048; j += 256) {
        int d = j >> 2, g = j & 3;                 // interleaved 4d+g
        g_bsum[j] = b_ih[g * 512 + d] + b_hh[g * 512 + d];
    }
    for (int i = tid; i < NT * NB; i += 256) {
        int t = i / NB, b = i % NB;
        g_capx[i] = caps[b * NL + t];
    }
    for (int j = tid; j < 16 * 32; j += 256) g_leaf[j] = 0;
    if (tid == 0) { g_cnt = 0; g_rel = 0; }
    __syncthreads();
    if (tid == 0) {
        int cnt = 0;
        for (int t = 0; t < NT; t++)
            for (int b = 0; b < NB; b++)
                if (t < lens[b] - 1) { g_rowA[cnt] = t * NB + b; g_rowO[cnt] = b * NT + t; cnt++; }
        g_nact[0] = cnt;
        for (int i = cnt; i < 2048; i++) { g_rowA[i] = 0; g_rowO[i] = 0; }
    }
}

// ---------------- build stacked/interleaved weights -------------------------
__global__ void wcat_kernel(const float* __restrict__ Wd, const float* __restrict__ Wb,
                            const float* __restrict__ Whh, const float* __restrict__ Wih)
{
    int f4 = blockIdx.x * blockDim.x + threadIdx.x;
    if (f4 < 3072 * 128) {
        int n = f4 >> 7, q = (f4 & 127) * 4;
        const float* src;
        if (n < 512)       src = Wd + n * 512 + q;
        else if (n < 1024) src = Wb + (n - 512) * 512 + q;
        else {
            int m = n - 1024, d = m >> 2, g = m & 3;
            src = Whh + (g * 512 + d) * 512 + q;
        }
        *(float4*)(g_WA + f4 * 4) = *(const float4*)src;
    } else if (f4 < 3072 * 128 + 2048 * 128) {
        int r = f4 - 3072 * 128;
        int n = r >> 7, q = (r & 127) * 4;
        int d = n >> 2, g = n & 3;
        *(float4*)(g_WCD + r * 4) = *(const float4*)(Wih + (g * 512 + d) * 768 + 256 + q);
    } else {
        int r = f4 - 3072 * 128 - 2048 * 128;
        if (r >= 2048 * 64) return;
        int n = r >> 6, q = (r & 63) * 4;
        int d = n >> 2, g = n & 3;
        *(float4*)(g_Wihx + r * 4) = *(const float4*)(Wih + (g * 512 + d) * 768 + q);
    }
}

// ============================================================================
// PERSISTENT RECURRENCE KERNEL — 128 blocks x 512 threads
// Two-level barrier arrival; mutable state via L2 (__ldcg/__stcg).
// ============================================================================
__device__ __forceinline__ void gbar(unsigned target)
{
    __syncthreads();
    if (threadIdx.x == 0) {
        unsigned* leaf = &g_leaf[(blockIdx.x & 15) * 32];
        unsigned p;
        asm volatile("atom.acq_rel.gpu.add.u32 %0, [%1], %2;"
                     : "=r"(p) : "l"(leaf), "r"(1u) : "memory");
        if (p == target * 8u - 1u) {                 // last in leaf group
            unsigned q;
            asm volatile("atom.acq_rel.gpu.add.u32 %0, [%1], %2;"
                         : "=r"(q) : "l"(&g_cnt), "r"(1u) : "memory");
            if (q == target * 16u - 1u) {            // last leaf -> release
                asm volatile("st.release.gpu.u32 [%0], %1;"
                             :: "l"(&g_rel), "r"(target) : "memory");
            }
        }
        unsigned v;
        do {
            asm volatile("ld.acquire.gpu.u32 %0, [%1];"
                         : "=r"(v) : "l"(&g_rel) : "memory");
        } while (v < target);
    }
    __syncthreads();
}

__global__ void __launch_bounds__(512, 1)
recurrence_kernel(const float* __restrict__ eo,
                  const float* __restrict__ b_dec_att,
                  const float* __restrict__ w_full,
                  const float* __restrict__ b_full,
                  const float* __restrict__ b_beta)
{
    __shared__ float sh[8448];                    // 33.8 KB, reused per phase
    int blk = blockIdx.x;
    int tid = threadIdx.x;

    for (int t = 0; t < NT; t++) {
        unsigned base = (unsigned)(t * 5);

        // ==== Phase A: pA[kz] = h @ WA^T partial.  16 n-tiles x 192 cols, 8 kz x 64k
        {
            int nt = blk & 15;
            int kz = blk >> 4;                     // 0..7
            int k0 = kz * 64;
            float (*As)[68]  = (float(*)[68])sh;              // [32][68]
            float (*Ws)[196] = (float(*)[196])(sh + 32 * 68); // [32][196]
            const float* Wbase = g_WA + (long long)nt * 192 * 512 + k0;

            // load indices
            int lb = tid >> 3, lkq = (tid & 7) * 4;           // h: b, k-quad
            int wc0 = tid >> 3, wk0 = (tid & 7) * 4;          // W idx i*512+tid: col=idx>>3,kq=(idx&7)*4

            // prefetch tile 0 (kk=0)
            float4 ar = __ldcg((const float4*)(g_h + lb * 512 + k0 + lkq));
            float4 wr[3];
#pragma unroll
            for (int i = 0; i < 3; i++) {
                int idx = i * 512 + tid;
                int col = idx >> 3, kq = (idx & 7) * 4;
                wr[i] = *(const float4*)(Wbase + (long long)col * 512 + kq);
            }
            As[lkq + 0][lb] = ar.x; As[lkq + 1][lb] = ar.y;
            As[lkq + 2][lb] = ar.z; As[lkq + 3][lb] = ar.w;
#pragma unroll
            for (int i = 0; i < 3; i++) {
                int idx = i * 512 + tid;
                int col = idx >> 3, kq = (idx & 7) * 4;
                Ws[kq + 0][col] = wr[i].x; Ws[kq + 1][col] = wr[i].y;
                Ws[kq + 2][col] = wr[i].z; Ws[kq + 3][col] = wr[i].w;
            }
            __syncthreads();

            int bi = tid & 15, ci = tid >> 4;      // b0 = bi*4, c0 = ci*6
            int b0 = bi * 4, c0 = ci * 6;
            float acc[4][6];
#pragma unroll
            for (int i = 0; i < 4; i++)
#pragma unroll
                for (int j = 0; j < 6; j++) acc[i][j] = 0.0f;

#pragma unroll
            for (int half = 0; half < 2; half++) {
                // prefetch tile 1 while computing tile 0
                float4 ar2; float4 wr2[3];
                if (half == 0) {
                    ar2 = __ldcg((const float4*)(g_h + lb * 512 + k0 + 32 + lkq));
#pragma unroll
                    for (int i = 0; i < 3; i++) {
                        int idx = i * 512 + tid;
                        int col = idx >> 3, kq = (idx & 7) * 4;
                        wr2[i] = *(const float4*)(Wbase + (long long)col * 512 + 32 + kq);
                    }
                }
#pragma unroll
                for (int k = 0; k < 32; k++) {
                    float a[4], w[6];
                    *(float4*)a = *(const float4*)&As[k][b0];
                    *(float2*)(w)     = *(const float2*)&Ws[k][c0];
                    *(float2*)(w + 2) = *(const float2*)&Ws[k][c0 + 2];
                    *(float2*)(w + 4) = *(const float2*)&Ws[k][c0 + 4];
#pragma unroll
                    for (int i = 0; i < 4; i++)
#pragma unroll
                        for (int j = 0; j < 6; j++)
                            acc[i][j] = fmaf(a[i], w[j], acc[i][j]);
                }
                __syncthreads();
                if (half == 0) {
                    As[lkq + 0][lb] = ar2.x; As[lkq + 1][lb] = ar2.y;
                    As[lkq + 2][lb] = ar2.z; As[lkq + 3][lb] = ar2.w;
#pragma unroll
                    for (int i = 0; i < 3; i++) {
                        int idx = i * 512 + tid;
                        int col = idx >> 3, kq = (idx & 7) * 4;
                        Ws[kq + 0][col] = wr2[i].x; Ws[kq + 1][col] = wr2[i].y;
                        Ws[kq + 2][col] = wr2[i].z; Ws[kq + 3][col] = wr2[i].w;
                    }
                    __syncthreads();
                }
            }
            float* dst = g_pA + ((long long)kz * NB) * 3072 + nt * 192 + c0;
#pragma unroll
            for (int i = 0; i < 4; i++) {
                float* row = dst + (long long)(b0 + i) * 3072;
                __stcg((float2*)(row),     make_float2(acc[i][0], acc[i][1]));
                __stcg((float2*)(row + 2), make_float2(acc[i][2], acc[i][3]));
                __stcg((float2*)(row + 4), make_float2(acc[i][4], acc[i][5]));
            }
        }
        gbar(base + 1);

        // ==== Phase B1: e scores. blk = b*2 + p-half; 4 threads/pixel ============
        {
            int b = blk >> 1, half = blk & 1;
            float* att2_s = sh;                   // 512
            float* w_s    = sh + 512;             // 512
            {
                float v = b_dec_att[tid];
#pragma unroll
                for (int kz = 0; kz < 8; kz++)
                    v += __ldcg(g_pA + ((long long)kz * NB + b) * 3072 + tid);
                att2_s[tid] = v;
                w_s[tid] = w_full[tid];
            }
            __syncthreads();

            int pl = tid >> 2;                    // 0..127
            int p  = half * 128 + pl;
            int ao = (tid & 3) * 128;
            const float* arow = g_att1 + ((long long)b * NP + p) * NE + ao;
            float acc = 0.0f;
#pragma unroll 4
            for (int a = 0; a < 128; a += 4) {
                float4 v4 = *(const float4*)(arow + a);
                acc = fmaf(fmaxf(v4.x + att2_s[ao + a + 0], 0.0f), w_s[ao + a + 0], acc);
                acc = fmaf(fmaxf(v4.y + att2_s[ao + a + 1], 0.0f), w_s[ao + a + 1], acc);
                acc = fmaf(fmaxf(v4.z + att2_s[ao + a + 2], 0.0f), w_s[ao + a + 2], acc);
                acc = fmaf(fmaxf(v4.w + att2_s[ao + a + 3], 0.0f), w_s[ao + a + 3], acc);
            }
            acc += __shfl_xor_sync(0xffffffffu, acc, 1);
            acc += __shfl_xor_sync(0xffffffffu, acc, 2);
            if ((tid & 3) == 0) __stcg(g_e + b * NP + p, acc + b_full[0]);
        }
        gbar(base + 2);

        // ==== Phase B2: softmax + gated awe. blk = b*2 + c-half ==================
        {
            int b = blk >> 1, ch = blk & 1;
            float* es     = sh;                   // 256
            float* red_s  = sh + 256;             // 256
            float* alpha_s= sh + 512;             // 256
            float* part_s = sh + 768;             // 256
            if (tid < 256) { es[tid] = __ldcg(g_e + b * NP + tid); red_s[tid] = 0.0f; }
            __syncthreads();
            if (tid < 256) red_s[tid] = es[tid];
            __syncthreads();
            for (int s = 128; s > 0; s >>= 1) {
                if (tid < s) red_s[tid] = fmaxf(red_s[tid], red_s[tid + s]);
                __syncthreads();
            }
            float mx = red_s[0];
            __syncthreads();
            float ex = 0.0f;
            if (tid < 256) { ex = expf(es[tid] - mx); red_s[tid] = ex; }
            __syncthreads();
            for (int s = 128; s > 0; s >>= 1) {
                if (tid < s) red_s[tid] += red_s[tid + s];
                __syncthreads();
            }
            if (tid < 256) alpha_s[tid] = ex / red_s[0];
            __syncthreads();

            int ci = tid & 255;
            int ph = tid >> 8;                    // 0 or 1 (p-half)
            int c = ch * 256 + ci;
            const float* erow = eo + ((long long)b * NE + c) * NP + ph * 128;
            const float* al   = alpha_s + ph * 128;
            float s = 0.0f;
#pragma unroll 4
            for (int p = 0; p < 128; p += 4) {
                float4 e4 = *(const float4*)(erow + p);
                s = fmaf(e4.x, al[p + 0], s);
                s = fmaf(e4.y, al[p + 1], s);
                s = fmaf(e4.z, al[p + 2], s);
                s = fmaf(e4.w, al[p + 3], s);
            }
            if (ph == 1) part_s[ci] = s;
            __syncthreads();
            if (ph == 0) {
                float total = s + part_s[ci];
                float gpre = b_beta[c];
#pragma unroll
                for (int kz = 0; kz < 8; kz++)
                    gpre += __ldcg(g_pA + ((long long)kz * NB + b) * 3072 + 512 + c);
                __stcg(g_awe + b * NE + c, sigf(gpre) * total);
            }
        }
        gbar(base + 3);

        // ==== Phase C: pC[kz] = awe @ WCD^T partial. 16 nt x 128 cols, 8 kz x 64k
        {
            int nt = blk & 15;
            int kz = blk >> 4;
            int k0 = kz * 64;
            float (*As)[68]  = (float(*)[68])sh;              // [32][68]
            float (*Ws)[132] = (float(*)[132])(sh + 32 * 68); // [32][132]
            const float* Wbase = g_WCD + (long long)nt * 128 * 512 + k0;

            int lb = tid >> 3, lkq = (tid & 7) * 4;

            float4 ar = __ldcg((const float4*)(g_awe + lb * 512 + k0 + lkq));
            float4 wr[2];
#pragma unroll
            for (int i = 0; i < 2; i++) {
                int idx = i * 512 + tid;
                int col = idx >> 3, kq = (idx & 7) * 4;
                wr[i] = *(const float4*)(Wbase + (long long)col * 512 + kq);
            }
            As[lkq + 0][lb] = ar.x; As[lkq + 1][lb] = ar.y;
            As[lkq + 2][lb] = ar.z; As[lkq + 3][lb] = ar.w;
#pragma unroll
            for (int i = 0; i < 2; i++) {
                int idx = i * 512 + tid;
                int col = idx >> 3, kq = (idx & 7) * 4;
                Ws[kq + 0][col] = wr[i].x; Ws[kq + 1][col] = wr[i].y;
                Ws[kq + 2][col] = wr[i].z; Ws[kq + 3][col] = wr[i].w;
            }
            __syncthreads();

            int bi = tid & 15, ci = tid >> 4;
            int b0 = bi * 4, c0 = ci * 4;
            float acc[4][4];
#pragma unroll
            for (int i = 0; i < 4; i++)
#pragma unroll
                for (int j = 0; j < 4; j++) acc[i][j] = 0.0f;

#pragma unroll
            for (int half = 0; half < 2; half++) {
                float4 ar2; float4 wr2[2];
                if (half == 0) {
                    ar2 = __ldcg((const float4*)(g_awe + lb * 512 + k0 + 32 + lkq));
#pragma unroll
                    for (int i = 0; i < 2; i++) {
                        int idx = i * 512 + tid;
                        int col = idx >> 3, kq = (idx & 7) * 4;
                        wr2[i] = *(const float4*)(Wbase + (long long)col * 512 + 32 + kq);
                    }
                }
#pragma unroll
                for (int k = 0; k < 32; k++) {
                    float a[4], w[4];
                    *(float4*)a = *(const float4*)&As[k][b0];
                    *(float4*)w = *(const float4*)&Ws[k][c0];
#pragma unroll
                    for (int i = 0; i < 4; i++)
#pragma unroll
                        for (int j = 0; j < 4; j++)
                            acc[i][j] = fmaf(a[i], w[j], acc[i][j]);
                }
                __syncthreads();
                if (half == 0) {
                    As[lkq + 0][lb] = ar2.x; As[lkq + 1][lb] = ar2.y;
                    As[lkq + 2][lb] = ar2.z; As[lkq + 3][lb] = ar2.w;
#pragma unroll
                    for (int i = 0; i < 2; i++) {
                        int idx = i * 512 + tid;
                        int col = idx >> 3, kq = (idx & 7) * 4;
                        Ws[kq + 0][col] = wr2[i].x; Ws[kq + 1][col] = wr2[i].y;
                        Ws[kq + 2][col] = wr2[i].z; Ws[kq + 3][col] = wr2[i].w;
                    }
                    __syncthreads();
                }
            }
            float* dst = g_pC + ((long long)kz * NB) * 2048 + nt * 128 + c0;
#pragma unroll
            for (int i = 0; i < 4; i++)
                __stcg((float4*)(dst + (long long)(b0 + i) * 2048),
                       make_float4(acc[i][0], acc[i][1], acc[i][2], acc[i][3]));
        }
        gbar(base + 4);

        // ==== Phase D: reduce partials + LSTM pointwise =========================
        if (tid < 256) {
            int idx = blk * 256 + tid;            // 0..32767
            int b = idx >> 9, d = idx & 511;
            float4 gv = *(const float4*)(g_xprj + (((long long)t * NB + b) * 2048) + 4 * d);
            float gi = gv.x, gf = gv.y, gg = gv.z, go = gv.w;
#pragma unroll
            for (int kz = 0; kz < 8; kz++) {
                float4 pa = __ldcg((const float4*)(g_pA + ((long long)kz * NB + b) * 3072 + 1024 + 4 * d));
                float4 pc = __ldcg((const float4*)(g_pC + ((long long)kz * NB + b) * 2048 + 4 * d));
                gi += pa.x + pc.x; gf += pa.y + pc.y;
                gg += pa.z + pc.z; go += pa.w + pc.w;
            }
            float cp = __ldcg(g_c + b * NE + d);
            float cn = sigf(gf) * cp + sigf(gi) * tanhf(gg);
            float hn = sigf(go) * tanhf(cn);
            __stcg(g_c + b * NE + d, cn);
            __stcg(g_h + b * NE + d, hn);
            g_Hall[((long long)t * NB + b) * NE + d] = hn;
        }
        gbar(base + 5);
    }
}

// ---------------- host launch -----------------------------------------------
extern "C" void kernel_launch(void* const* d_in, const int* in_sizes, int n_in,
                              void* d_out, int out_size)
{
    const float* eo        = (const float*)d_in[0];
    const int*   caps      = (const int*)  d_in[1];
    const int*   lens      = (const int*)  d_in[2];
    const float* W_enc_att = (const float*)d_in[3];
    const float* b_enc_att = (const float*)d_in[4];
    const float* W_dec_att = (const float*)d_in[5];
    const float* b_dec_att = (const float*)d_in[6];
    const float* w_full    = (const float*)d_in[7];
    const float* b_full    = (const float*)d_in[8];
    const float* emb       = (const float*)d_in[9];
    const float* W_ih      = (const float*)d_in[10];
    const float* W_hh      = (const float*)d_in[11];
    const float* b_ih      = (const float*)d_in[12];
    const float* b_hh      = (const float*)d_in[13];
    const float* W_init_h  = (const float*)d_in[14];
    const float* b_init_h  = (const float*)d_in[15];
    const float* W_init_c  = (const float*)d_in[16];
    const float* b_init_c  = (const float*)d_in[17];
    const float* W_beta    = (const float*)d_in[18];
    const float* b_beta    = (const float*)d_in[19];
    const float* W_fc      = (const float*)d_in[20];
    const float* b_fc      = (const float*)d_in[21];
    float* out = (float*)d_out;

    float *enc, *att1, *mean, *h, *c, *Hall, *xprj, *bsum, *Wihx;
    int *capx, *rowA, *rowO, *nact;
    cudaGetSymbolAddress((void**)&enc,  g_enc);
    cudaGetSymbolAddress((void**)&att1, g_att1);
    cudaGetSymbolAddress((void**)&mean, g_mean);
    cudaGetSymbolAddress((void**)&h,    g_h);
    cudaGetSymbolAddress((void**)&c,    g_c);
    cudaGetSymbolAddress((void**)&Hall, g_Hall);
    cudaGetSymbolAddress((void**)&xprj, g_xprj);
    cudaGetSymbolAddress((void**)&bsum, g_bsum);
    cudaGetSymbolAddress((void**)&Wihx, g_Wihx);
    cudaGetSymbolAddress((void**)&capx, g_capx);
    cudaGetSymbolAddress((void**)&rowA, g_rowA);
    cudaGetSymbolAddress((void**)&rowO, g_rowO);
    cudaGetSymbolAddress((void**)&nact, g_nact);

    cudaMemsetAsync(out, 0, (size_t)out_size * sizeof(float));

    transpose_enc<<<dim3(16, 8, 64), dim3(32, 8)>>>(eo, enc);
    mean_kernel<<<4096, dim3(32, 8)>>>(eo, mean);
    setup_kernel<<<1, 256>>>(caps, lens, b_ih, b_hh);

    // att1 = enc @ W_enc_att^T + b   (M=16384, N=512, K=512)
    sgemm128<<<dim3(128, 4), 256>>>(enc, 512, nullptr, W_enc_att, 512, b_enc_att,
                                    att1, 512, nullptr, NB * NP, nullptr, 512);

    wcat_kernel<<<3072, 256>>>(W_dec_att, W_beta, W_hh, W_ih);

    sgemm64<<<dim3(1, 8), 256>>>(mean, 512, W_init_h, 512, b_init_h, h, 512, 512);
    sgemm64<<<dim3(1, 8), 256>>>(mean, 512, W_init_c, 512, b_init_c, c, 512, 512);

    // x_proj = emb[cap] @ Wihx^T + bsum (interleaved), K=256
    sgemm128<<<dim3(16, 16), 256>>>(emb, 256, capx, Wihx, 256, bsum,
                                    xprj, 2048, nullptr, NT * NB, nullptr, 256);

    // fused 31-step recurrence (persistent, 512 threads, tree barriers)
    recurrence_kernel<<<GRIDN, 512>>>(eo, b_dec_att, w_full, b_full, b_beta);

    // Final FC over compacted active rows
    sgemm128<<<dim3(16, 125), 256>>>(Hall, 512, rowA, W_fc, 512, b_fc,
                                     out, NV, rowO, NT * NB, nact, 512);
}